// round 10
// baseline (speedup 1.0000x reference)
#include <cuda_runtime.h>
#include <cuda_fp16.h>
#include <cstdint>

#define B_    16384
#define CURD  2048
#define FEAT_ 2048
#define HEADS_ 16
#define HDIM  128

#define NTHREADS 256
#define BM 128
#define BN 256
#define BK 64
// per stage: A 128 rows x 128B = 16 KB, B 256 rows x 128B = 32 KB
#define A_STAGE   16384
#define B_STAGE   32768
#define STAGE_B   (A_STAGE + B_STAGE)     // 48 KB
#define NSTAGE 3
#define SMEM_BYTES (NSTAGE*STAGE_B)       // 144 KB

// ---------------- scratch (device globals; no allocation allowed) ----------
__device__ __align__(16) __half g_xh [(size_t)B_*CURD];
__device__ __align__(16) __half g_v2h[(size_t)B_*FEAT_];
__device__ __align__(16) __half g_v3h[(size_t)B_*FEAT_];
__device__ __align__(16) __half g_wqh [(size_t)FEAT_*CURD];
__device__ __align__(16) __half g_wk2h[(size_t)FEAT_*FEAT_];
__device__ __align__(16) __half g_wv2h[(size_t)FEAT_*FEAT_];
__device__ __align__(16) __half g_wk3h[(size_t)FEAT_*FEAT_];
__device__ __align__(16) __half g_wv3h[(size_t)FEAT_*FEAT_];
__device__ __align__(16) __half g_woh [(size_t)CURD*FEAT_];
__device__ __align__(16) __half g_q  [(size_t)B_*FEAT_];
__device__ __align__(16) __half g_kv2[(size_t)B_*2*FEAT_];
__device__ __align__(16) __half g_kv3[(size_t)B_*2*FEAT_];
__device__ __align__(16) __half g_att[(size_t)B_*FEAT_];
__device__ __align__(16) float  g_y  [(size_t)B_*CURD];

// ---------------- helpers ----------------
__device__ __forceinline__ void cpa16(uint32_t s, const void* g) {
    asm volatile("cp.async.cg.shared.global [%0], [%1], 16;\n" :: "r"(s), "l"(g));
}

__device__ __forceinline__ void ldsm4(uint32_t* r, uint32_t addr) {
    asm volatile("ldmatrix.sync.aligned.m8n8.x4.shared.b16 {%0,%1,%2,%3}, [%4];"
        : "=r"(r[0]), "=r"(r[1]), "=r"(r[2]), "=r"(r[3]) : "r"(addr));
}

__device__ __forceinline__ void mma_f16(float* c, const uint32_t* a, const uint32_t* b) {
    asm volatile(
        "mma.sync.aligned.m16n8k16.row.col.f32.f16.f16.f32 "
        "{%0,%1,%2,%3}, {%4,%5,%6,%7}, {%8,%9}, {%0,%1,%2,%3};"
        : "+f"(c[0]), "+f"(c[1]), "+f"(c[2]), "+f"(c[3])
        : "r"(a[0]), "r"(a[1]), "r"(a[2]), "r"(a[3]),
          "r"(b[0]), "r"(b[1]));
}

// ---------------- fp32 -> fp16 conversion (RN) ------------------------------
__global__ void conv_h_kernel(const float* __restrict__ in,
                              __half* __restrict__ out, long long n4) {
    long long i  = blockIdx.x * (long long)blockDim.x + threadIdx.x;
    long long st = (long long)gridDim.x * blockDim.x;
    const float4* in4 = (const float4*)in;
    __half2* o2 = (__half2*)out;
    for (; i < n4; i += st) {
        float4 v = in4[i];
        o2[2*i]   = __floats2half2_rn(v.x, v.y);
        o2[2*i+1] = __floats2half2_rn(v.z, v.w);
    }
}

// ---------------- FP16 GEMM:  C[M,N] = A[M,K] @ W[N,K]^T + bias (+res)
// CTA tile 128x256, warp grid 2(M) x 4(N), warp tile 64x64.
// SW128-swizzled smem, ldmatrix loads, 3-stage cp.async pipeline.
// W split into two stacked halves (W0 rows [0,Nsplit), W1 the rest).
template<bool RES, bool HOUT>
__global__ __launch_bounds__(NTHREADS, 1)
void gemm_f16_kernel(const __half* __restrict__ A,
                     const __half* __restrict__ W0,
                     const __half* __restrict__ W1,
                     int Nsplit,
                     const float* __restrict__ bias0,
                     const float* __restrict__ bias1,
                     const float* __restrict__ res,
                     void* __restrict__ Cv,
                     int N, int K) {
    extern __shared__ __align__(1024) char smem[];
    const uint32_t sbase = (uint32_t)__cvta_generic_to_shared(smem);

    const int nb = blockIdx.x, mb = blockIdx.y;
    const __half* Wp; const float* biasP; int nloc0;
    if (nb*BN < Nsplit) { Wp = W0; biasP = bias0; nloc0 = nb*BN; }
    else                { Wp = W1; biasP = bias1; nloc0 = nb*BN - Nsplit; }

    const int tid  = threadIdx.x;
    const int warp = tid >> 5, lane = tid & 31;
    const int wm = warp & 1;           // 2 M-rows of warps (64 rows each)
    const int wn = warp >> 1;          // 4 N-cols of warps (64 cols each)
    const int qr = lane >> 2, qc = lane & 3;

    // ---- staging addressing ----
    // A: 16 KB/stage -> each thread one half-row (64 B = 4 x 16B chunks)
    const int arow = tid >> 1;
    const int acol = (tid & 1) * 64;
    const uint32_t axor = (uint32_t)((arow & 7) << 4);
    const __half* Ag = A + (size_t)(mb*BM + arow)*K + acol/2;
    // B: 32 KB/stage -> each thread one full row (128 B = 8 x 16B chunks)
    const int brow = tid;
    const uint32_t bxor = (uint32_t)((brow & 7) << 4);
    const __half* Bg = Wp + (size_t)(nloc0 + brow)*K;

    // ---- ldmatrix addressing ----
    const int j  = lane >> 3;          // matrix index 0..3
    const int rr = lane & 7;
    const uint32_t fxor = (uint32_t)(rr << 4);
    const uint32_t aRow  = (uint32_t)(wm*64 + (j&1)*8 + rr);
    const uint32_t aKoff = (uint32_t)((j>>1)*16);
    const uint32_t bRow  = (uint32_t)(wn*64 + (j>>1)*8 + rr);
    const uint32_t bKoff = (uint32_t)((j&1)*16);

    float acc[4][8][4];
    #pragma unroll
    for (int i = 0; i < 4; i++)
        #pragma unroll
        for (int jn = 0; jn < 8; jn++)
            #pragma unroll
            for (int l = 0; l < 4; l++) acc[i][jn][l] = 0.f;

    const int KT = K / BK;   // 32

    // ---- copy one stage (per thread) ----
    auto copy_stage = [&](int kt, int st) {
        const uint32_t sA = sbase + st*STAGE_B;
        const uint32_t sB = sA + A_STAGE;
        const __half* Agk = Ag + kt*BK;
        const __half* Bgk = Bg + kt*BK;
        #pragma unroll
        for (int i = 0; i < 4; i++) {
            uint32_t c = ((uint32_t)(acol + i*16)) ^ axor;
            cpa16(sA + arow*128 + c, Agk + i*8);
        }
        #pragma unroll
        for (int i = 0; i < 8; i++) {
            uint32_t c = ((uint32_t)(i*16)) ^ bxor;
            cpa16(sB + brow*128 + c, Bgk + i*8);
        }
        asm volatile("cp.async.commit_group;\n" ::);
    };

    // ---- prologue: issue stages 0,1 ----
    copy_stage(0, 0);
    copy_stage(1, 1);

    for (int kt = 0; kt < KT; kt++) {
        const int st = kt % NSTAGE;
        if (kt < KT-1) { asm volatile("cp.async.wait_group 1;\n" ::); }
        else           { asm volatile("cp.async.wait_group 0;\n" ::); }
        __syncthreads();
        if (kt + 2 < KT) copy_stage(kt+2, (kt+2) % NSTAGE);

        const uint32_t aBase = sbase + st*STAGE_B + aRow*128;
        const uint32_t bBase = sbase + st*STAGE_B + A_STAGE + bRow*128;
        #pragma unroll
        for (int ks = 0; ks < BK/16; ks++) {
            uint32_t afr[4][4];
            const uint32_t ac = ((uint32_t)(ks*32) + aKoff) ^ fxor;
            #pragma unroll
            for (int mt = 0; mt < 4; mt++)
                ldsm4(afr[mt], aBase + mt*16*128 + ac);
            uint32_t bfr[16];
            const uint32_t bc = ((uint32_t)(ks*32) + bKoff) ^ fxor;
            #pragma unroll
            for (int t = 0; t < 4; t++)
                ldsm4(bfr + t*4, bBase + t*16*128 + bc);
            #pragma unroll
            for (int mt = 0; mt < 4; mt++)
                #pragma unroll
                for (int nt = 0; nt < 8; nt++)
                    mma_f16(acc[mt][nt], afr[mt], bfr + nt*2);
        }
        __syncthreads();
    }

    // ---- epilogue: bias (+residual), fp16 or fp32 stores ----
    float bv0[8], bv1[8];
    #pragma unroll
    for (int nt = 0; nt < 8; nt++) {
        int cl = nloc0 + wn*64 + nt*8 + qc*2;
        bv0[nt] = biasP[cl];
        bv1[nt] = biasP[cl + 1];
    }
    #pragma unroll
    for (int mt = 0; mt < 4; mt++) {
        int r0 = mb*BM + wm*64 + mt*16 + qr;
        #pragma unroll
        for (int nt = 0; nt < 8; nt++) {
            int c0 = nb*BN + wn*64 + nt*8 + qc*2;
            size_t o0 = (size_t)r0*N + c0;
            size_t o1 = o0 + (size_t)8*N;
            float v0 = acc[mt][nt][0] + bv0[nt];
            float v1 = acc[mt][nt][1] + bv1[nt];
            float v2 = acc[mt][nt][2] + bv0[nt];
            float v3 = acc[mt][nt][3] + bv1[nt];
            if (HOUT) {
                __half* C = (__half*)Cv;
                *(__half2*)(C + o0) = __floats2half2_rn(v0, v1);
                *(__half2*)(C + o1) = __floats2half2_rn(v2, v3);
            } else {
                float* C = (float*)Cv;
                if (RES) {
                    v0 += res[o0]; v1 += res[o0 + 1];
                    v2 += res[o1]; v3 += res[o1 + 1];
                }
                *(float2*)(C + o0) = make_float2(v0, v1);
                *(float2*)(C + o1) = make_float2(v2, v3);
            }
        }
    }
}

// ---------------- attention: one warp per (b, h); 2-key softmax -----------
__global__ void attn_kernel(const __half* __restrict__ q,
                            const __half* __restrict__ kv2,
                            const __half* __restrict__ kv3,
                            __half* __restrict__ attn,
                            float* __restrict__ wout) {
    int gw   = (blockIdx.x * blockDim.x + threadIdx.x) >> 5;   // b*16 + h
    int lane = threadIdx.x & 31;
    int b = gw >> 4;
    int h = gw & 15;
    size_t qoff = (size_t)b*FEAT_     + h*HDIM + lane*4;
    size_t koff = (size_t)b*(2*FEAT_) + h*HDIM + lane*4;

    uint2 qr = *(const uint2*)(q   + qoff);
    uint2 k2r = *(const uint2*)(kv2 + koff);
    uint2 k3r = *(const uint2*)(kv3 + koff);
    uint2 v2r = *(const uint2*)(kv2 + koff + FEAT_);
    uint2 v3r = *(const uint2*)(kv3 + koff + FEAT_);

    float2 qa = __half22float2(*(__half2*)&qr.x);
    float2 qb = __half22float2(*(__half2*)&qr.y);
    float2 k2a = __half22float2(*(__half2*)&k2r.x);
    float2 k2b = __half22float2(*(__half2*)&k2r.y);
    float2 k3a = __half22float2(*(__half2*)&k3r.x);
    float2 k3b = __half22float2(*(__half2*)&k3r.y);
    float2 v2a = __half22float2(*(__half2*)&v2r.x);
    float2 v2b = __half22float2(*(__half2*)&v2r.y);
    float2 v3a = __half22float2(*(__half2*)&v3r.x);
    float2 v3b = __half22float2(*(__half2*)&v3r.y);

    float s2 = qa.x*k2a.x + qa.y*k2a.y + qb.x*k2b.x + qb.y*k2b.y;
    float s3 = qa.x*k3a.x + qa.y*k3a.y + qb.x*k3b.x + qb.y*k3b.y;
    #pragma unroll
    for (int o = 16; o; o >>= 1) {
        s2 += __shfl_xor_sync(0xffffffffu, s2, o);
        s3 += __shfl_xor_sync(0xffffffffu, s3, o);
    }
    const float scale = 0.08838834764831845f;   // 1/sqrt(128)
    s2 *= scale; s3 *= scale;
    float m  = fmaxf(s2, s3);
    float e2 = expf(s2 - m), e3 = expf(s3 - m);
    float inv = 1.f / (e2 + e3);
    float w2 = e2 * inv, w3 = e3 * inv;

    __half2 p0 = __floats2half2_rn(w2*v2a.x + w3*v3a.x, w2*v2a.y + w3*v3a.y);
    __half2 p1 = __floats2half2_rn(w2*v2b.x + w3*v3b.x, w2*v2b.y + w3*v3b.y);
    uint2 ov;
    ov.x = *(uint32_t*)&p0;
    ov.y = *(uint32_t*)&p1;
    *(uint2*)(attn + qoff) = ov;

    if (lane == 0) {
        wout[(size_t)gw*2]     = w2;
        wout[(size_t)gw*2 + 1] = w3;
    }
}

// ---------------- LayerNorm: one block per row ----------------------------
__global__ void ln_kernel(const float* __restrict__ y,
                          const float* __restrict__ lw,
                          const float* __restrict__ lb,
                          float* __restrict__ out) {
    __shared__ float shs[8], shq[8];
    int row = blockIdx.x, t = threadIdx.x;
    const float4* yr = (const float4*)(y + (size_t)row*CURD);
    float4 a = yr[t];
    float4 b = yr[256 + t];
    float s  = a.x+a.y+a.z+a.w + b.x+b.y+b.z+b.w;
    float qq = a.x*a.x+a.y*a.y+a.z*a.z+a.w*a.w
             + b.x*b.x+b.y*b.y+b.z*b.z+b.w*b.w;
    #pragma unroll
    for (int o = 16; o; o >>= 1) {
        s  += __shfl_xor_sync(0xffffffffu, s,  o);
        qq += __shfl_xor_sync(0xffffffffu, qq, o);
    }
    int warp = t >> 5;
    if ((t & 31) == 0) { shs[warp] = s; shq[warp] = qq; }
    __syncthreads();
    float S = 0.f, Q = 0.f;
    #pragma unroll
    for (int i = 0; i < 8; i++) { S += shs[i]; Q += shq[i]; }
    float mean = S * (1.f/2048.f);
    float inv  = rsqrtf(Q * (1.f/2048.f) - mean*mean + 1e-5f);

    const float4* lw4 = (const float4*)lw;
    const float4* lb4 = (const float4*)lb;
    float4* orow = (float4*)(out + (size_t)row*CURD);
    float4 w, z, o4;
    w = lw4[t];       z = lb4[t];
    o4.x = w.x*(a.x-mean)*inv + z.x;
    o4.y = w.y*(a.y-mean)*inv + z.y;
    o4.z = w.z*(a.z-mean)*inv + z.z;
    o4.w = w.w*(a.w-mean)*inv + z.w;
    orow[t] = o4;
    w = lw4[256+t];   z = lb4[256+t];
    o4.x = w.x*(b.x-mean)*inv + z.x;
    o4.y = w.y*(b.y-mean)*inv + z.y;
    o4.z = w.z*(b.z-mean)*inv + z.z;
    o4.w = w.w*(b.w-mean)*inv + z.w;
    orow[256+t] = o4;
}

// ---------------- launch ---------------------------------------------------
extern "C" void kernel_launch(void* const* d_in, const int* in_sizes, int n_in,
                              void* d_out, int out_size) {
    const float* x   = (const float*)d_in[0];
    const float* v2  = (const float*)d_in[1];
    const float* v3  = (const float*)d_in[2];
    const float* Wq  = (const float*)d_in[3];
    const float* bq  = (const float*)d_in[4];
    const float* Wk2 = (const float*)d_in[5];
    const float* bk2 = (const float*)d_in[6];
    const float* Wk3 = (const float*)d_in[7];
    const float* bk3 = (const float*)d_in[8];
    const float* Wv2 = (const float*)d_in[9];
    const float* bv2 = (const float*)d_in[10];
    const float* Wv3 = (const float*)d_in[11];
    const float* bv3 = (const float*)d_in[12];
    const float* Wo  = (const float*)d_in[13];
    const float* bo  = (const float*)d_in[14];
    const float* lw  = (const float*)d_in[15];
    const float* lb  = (const float*)d_in[16];
    float* out = (float*)d_out;

    __half *xh, *v2h, *v3h, *wqh, *wk2h, *wv2h, *wk3h, *wv3h, *woh;
    __half *qb, *kv2, *kv3, *attn;
    float *yb;
    cudaGetSymbolAddress((void**)&xh,   g_xh);
    cudaGetSymbolAddress((void**)&v2h,  g_v2h);
    cudaGetSymbolAddress((void**)&v3h,  g_v3h);
    cudaGetSymbolAddress((void**)&wqh,  g_wqh);
    cudaGetSymbolAddress((void**)&wk2h, g_wk2h);
    cudaGetSymbolAddress((void**)&wv2h, g_wv2h);
    cudaGetSymbolAddress((void**)&wk3h, g_wk3h);
    cudaGetSymbolAddress((void**)&wv3h, g_wv3h);
    cudaGetSymbolAddress((void**)&woh,  g_woh);
    cudaGetSymbolAddress((void**)&qb,   g_q);
    cudaGetSymbolAddress((void**)&kv2,  g_kv2);
    cudaGetSymbolAddress((void**)&kv3,  g_kv3);
    cudaGetSymbolAddress((void**)&attn, g_att);
    cudaGetSymbolAddress((void**)&yb,   g_y);

    cudaFuncSetAttribute((const void*)gemm_f16_kernel<false,true>,
                         cudaFuncAttributeMaxDynamicSharedMemorySize, SMEM_BYTES);
    cudaFuncSetAttribute((const void*)gemm_f16_kernel<true,false>,
                         cudaFuncAttributeMaxDynamicSharedMemorySize, SMEM_BYTES);

    const int RG = 2048, RT = 256;
    conv_h_kernel<<<RG, RT>>>(x,   xh,  (long long)B_*CURD/4);
    conv_h_kernel<<<RG, RT>>>(v2,  v2h, (long long)B_*FEAT_/4);
    conv_h_kernel<<<RG, RT>>>(v3,  v3h, (long long)B_*FEAT_/4);
    conv_h_kernel<<<RG, RT>>>(Wq,  wqh, (long long)FEAT_*CURD/4);
    conv_h_kernel<<<RG, RT>>>(Wk2, wk2h,(long long)FEAT_*FEAT_/4);
    conv_h_kernel<<<RG, RT>>>(Wv2, wv2h,(long long)FEAT_*FEAT_/4);
    conv_h_kernel<<<RG, RT>>>(Wk3, wk3h,(long long)FEAT_*FEAT_/4);
    conv_h_kernel<<<RG, RT>>>(Wv3, wv3h,(long long)FEAT_*FEAT_/4);
    conv_h_kernel<<<RG, RT>>>(Wo,  woh, (long long)CURD*FEAT_/4);

    dim3 blk(NTHREADS);
    // q = x @ Wq^T + bq          (fp16 out)
    gemm_f16_kernel<false,true><<<dim3(FEAT_/BN, B_/BM), blk, SMEM_BYTES>>>(
        xh, wqh, wqh, FEAT_, bq, bq, nullptr, qb, FEAT_, CURD);
    // [k2 | v2] = v2 @ [Wk2; Wv2]^T + [bk2; bv2]   (fp16 out)
    gemm_f16_kernel<false,true><<<dim3(2*FEAT_/BN, B_/BM), blk, SMEM_BYTES>>>(
        v2h, wk2h, wv2h, FEAT_, bk2, bv2, nullptr, kv2, 2*FEAT_, FEAT_);
    // [k3 | v3] = v3 @ [Wk3; Wv3]^T + [bk3; bv3]   (fp16 out)
    gemm_f16_kernel<false,true><<<dim3(2*FEAT_/BN, B_/BM), blk, SMEM_BYTES>>>(
        v3h, wk3h, wv3h, FEAT_, bk3, bv3, nullptr, kv3, 2*FEAT_, FEAT_);

    // attention + attn_weights (written to the tail of d_out)
    size_t woff = (size_t)out_size - (size_t)B_*HEADS_*2;
    attn_kernel<<<B_*HEADS_/8, 256>>>(qb, kv2, kv3, attn, out + woff);

    // y = x + attn @ Wo^T + bo   (residual fused, exact fp32 x; fp32 out)
    gemm_f16_kernel<true,false><<<dim3(CURD/BN, B_/BM), blk, SMEM_BYTES>>>(
        attn, woh, woh, CURD, bo, bo, x, yb, CURD, FEAT_);

    // LayerNorm -> d_out
    ln_kernel<<<B_, 256>>>(yb, lw, lb, out);
}

// round 11
// speedup vs baseline: 1.2634x; 1.2634x over previous
#include <cuda_runtime.h>
#include <cuda_fp16.h>
#include <cstdint>

#define B_    16384
#define CURD  2048
#define FEAT_ 2048
#define HEADS_ 16
#define HDIM  128

#define NTHREADS 256
#define BM 128
#define BN 128
#define BK 64
// per stage: A 128 rows x 128B = 16 KB, B 128 rows x 128B = 16 KB
#define A_STAGE   16384
#define STAGE_B   (2*A_STAGE)          // 32 KB
#define NSTAGE 3
#define SMEM_BYTES (NSTAGE*STAGE_B)    // 96 KB -> 2 CTAs/SM

// ---------------- scratch (device globals; no allocation allowed) ----------
__device__ __align__(16) __half g_xh [(size_t)B_*CURD];
__device__ __align__(16) __half g_v2h[(size_t)B_*FEAT_];
__device__ __align__(16) __half g_v3h[(size_t)B_*FEAT_];
__device__ __align__(16) __half g_wqh [(size_t)FEAT_*CURD];
__device__ __align__(16) __half g_wk2h[(size_t)FEAT_*FEAT_];
__device__ __align__(16) __half g_wv2h[(size_t)FEAT_*FEAT_];
__device__ __align__(16) __half g_wk3h[(size_t)FEAT_*FEAT_];
__device__ __align__(16) __half g_wv3h[(size_t)FEAT_*FEAT_];
__device__ __align__(16) __half g_woh [(size_t)CURD*FEAT_];
__device__ __align__(16) __half g_q  [(size_t)B_*FEAT_];
__device__ __align__(16) __half g_kv2[(size_t)B_*2*FEAT_];
__device__ __align__(16) __half g_kv3[(size_t)B_*2*FEAT_];
__device__ __align__(16) __half g_att[(size_t)B_*FEAT_];
__device__ __align__(16) float  g_y  [(size_t)B_*CURD];

// ---------------- helpers ----------------
__device__ __forceinline__ void cpa16(uint32_t s, const void* g) {
    asm volatile("cp.async.cg.shared.global [%0], [%1], 16;\n" :: "r"(s), "l"(g));
}

__device__ __forceinline__ void ldsm4(uint32_t* r, uint32_t addr) {
    asm volatile("ldmatrix.sync.aligned.m8n8.x4.shared.b16 {%0,%1,%2,%3}, [%4];"
        : "=r"(r[0]), "=r"(r[1]), "=r"(r[2]), "=r"(r[3]) : "r"(addr));
}

__device__ __forceinline__ void mma_f16(float* c, const uint32_t* a, const uint32_t* b) {
    asm volatile(
        "mma.sync.aligned.m16n8k16.row.col.f32.f16.f16.f32 "
        "{%0,%1,%2,%3}, {%4,%5,%6,%7}, {%8,%9}, {%0,%1,%2,%3};"
        : "+f"(c[0]), "+f"(c[1]), "+f"(c[2]), "+f"(c[3])
        : "r"(a[0]), "r"(a[1]), "r"(a[2]), "r"(a[3]),
          "r"(b[0]), "r"(b[1]));
}

// ---------------- fp32 -> fp16 conversion (RN) ------------------------------
__global__ void conv_h_kernel(const float* __restrict__ in,
                              __half* __restrict__ out, long long n4) {
    long long i  = blockIdx.x * (long long)blockDim.x + threadIdx.x;
    long long st = (long long)gridDim.x * blockDim.x;
    const float4* in4 = (const float4*)in;
    __half2* o2 = (__half2*)out;
    for (; i < n4; i += st) {
        float4 v = in4[i];
        o2[2*i]   = __floats2half2_rn(v.x, v.y);
        o2[2*i+1] = __floats2half2_rn(v.z, v.w);
    }
}

// ---------------- FP16 GEMM:  C[M,N] = A[M,K] @ W[N,K]^T + bias (+res)
// CTA tile 128x128, warp grid 2(M) x 4(N), warp tile 64x32, 2 CTAs/SM.
// SW128-swizzled smem, ldmatrix loads, 3-stage cp.async pipeline (2-ahead).
// W split into two stacked halves (W0 rows [0,Nsplit), W1 the rest).
template<bool RES, bool HOUT>
__global__ __launch_bounds__(NTHREADS, 2)
void gemm_f16_kernel(const __half* __restrict__ A,
                     const __half* __restrict__ W0,
                     const __half* __restrict__ W1,
                     int Nsplit,
                     const float* __restrict__ bias0,
                     const float* __restrict__ bias1,
                     const float* __restrict__ res,
                     void* __restrict__ Cv,
                     int N, int K) {
    extern __shared__ __align__(1024) char smem[];
    const uint32_t sbase = (uint32_t)__cvta_generic_to_shared(smem);

    const int nb = blockIdx.x, mb = blockIdx.y;
    const __half* Wp; const float* biasP; int nloc0;
    if (nb*BN < Nsplit) { Wp = W0; biasP = bias0; nloc0 = nb*BN; }
    else                { Wp = W1; biasP = bias1; nloc0 = nb*BN - Nsplit; }

    const int tid  = threadIdx.x;
    const int warp = tid >> 5, lane = tid & 31;
    const int wm = warp & 1;           // 2 M-rows of warps (64 rows each)
    const int wn = warp >> 1;          // 4 N-cols of warps (32 cols each)
    const int qr = lane >> 2, qc = lane & 3;

    // ---- staging addressing (per thread: one half-row = 64B = 4x16B) ----
    const int srow = tid >> 1;                  // 0..127
    const int scol = (tid & 1) * 64;            // byte col 0 or 64
    const uint32_t sxor = (uint32_t)((srow & 7) << 4);
    const __half* Ag = A  + (size_t)(mb*BM + srow)*K + scol/2;
    const __half* Bg = Wp + (size_t)(nloc0 + srow)*K + scol/2;

    // ---- ldmatrix addressing ----
    const int j  = lane >> 3;          // matrix index 0..3
    const int rr = lane & 7;
    const uint32_t fxor = (uint32_t)(rr << 4);
    const uint32_t aRow  = (uint32_t)(wm*64 + (j&1)*8 + rr);
    const uint32_t aKoff = (uint32_t)((j>>1)*16);
    const uint32_t bRow  = (uint32_t)(wn*32 + (j>>1)*8 + rr);
    const uint32_t bKoff = (uint32_t)((j&1)*16);

    float acc[4][4][4];
    #pragma unroll
    for (int i = 0; i < 4; i++)
        #pragma unroll
        for (int jn = 0; jn < 4; jn++)
            #pragma unroll
            for (int l = 0; l < 4; l++) acc[i][jn][l] = 0.f;

    const int KT = K / BK;

    // ---- copy one BK stage (per thread: 4 A chunks + 4 B chunks) ----
    auto copy_stage = [&](int kt, int st) {
        const uint32_t sA = sbase + st*STAGE_B;
        const uint32_t sB = sA + A_STAGE;
        const __half* Agk = Ag + kt*BK;
        const __half* Bgk = Bg + kt*BK;
        #pragma unroll
        for (int i = 0; i < 4; i++) {
            uint32_t c = ((uint32_t)(scol + i*16)) ^ sxor;
            cpa16(sA + srow*128 + c, Agk + i*8);
            cpa16(sB + srow*128 + c, Bgk + i*8);
        }
        asm volatile("cp.async.commit_group;\n" ::);
    };

    // ---- prologue: issue stages 0,1 ----
    copy_stage(0, 0);
    copy_stage(1, 1);

    for (int kt = 0; kt < KT; kt++) {
        const int st = kt % NSTAGE;
        if (kt < KT-1) { asm volatile("cp.async.wait_group 1;\n" ::); }
        else           { asm volatile("cp.async.wait_group 0;\n" ::); }
        __syncthreads();    // also guards buffer reuse for the copy below
        if (kt + 2 < KT) copy_stage(kt+2, (kt+2) % NSTAGE);

        const uint32_t aBase = sbase + st*STAGE_B + aRow*128;
        const uint32_t bBase = sbase + st*STAGE_B + A_STAGE + bRow*128;
        #pragma unroll
        for (int ks = 0; ks < BK/16; ks++) {
            uint32_t afr[4][4];
            const uint32_t ac = ((uint32_t)(ks*32) + aKoff) ^ fxor;
            #pragma unroll
            for (int mt = 0; mt < 4; mt++)
                ldsm4(afr[mt], aBase + mt*16*128 + ac);
            uint32_t bfr[8];
            const uint32_t bc = ((uint32_t)(ks*32) + bKoff) ^ fxor;
            ldsm4(bfr,     bBase + bc);             // n-subtiles 0,1
            ldsm4(bfr + 4, bBase + 16*128 + bc);    // n-subtiles 2,3
            #pragma unroll
            for (int mt = 0; mt < 4; mt++)
                #pragma unroll
                for (int nt = 0; nt < 4; nt++)
                    mma_f16(acc[mt][nt], afr[mt], bfr + nt*2);
        }
    }

    // ---- epilogue: bias (+residual), fp16 or fp32 stores ----
    float bv0[4], bv1[4];
    #pragma unroll
    for (int nt = 0; nt < 4; nt++) {
        int cl = nloc0 + wn*32 + nt*8 + qc*2;
        bv0[nt] = biasP[cl];
        bv1[nt] = biasP[cl + 1];
    }
    #pragma unroll
    for (int mt = 0; mt < 4; mt++) {
        int r0 = mb*BM + wm*64 + mt*16 + qr;
        #pragma unroll
        for (int nt = 0; nt < 4; nt++) {
            int c0 = nb*BN + wn*32 + nt*8 + qc*2;
            size_t o0 = (size_t)r0*N + c0;
            size_t o1 = o0 + (size_t)8*N;
            float v0 = acc[mt][nt][0] + bv0[nt];
            float v1 = acc[mt][nt][1] + bv1[nt];
            float v2 = acc[mt][nt][2] + bv0[nt];
            float v3 = acc[mt][nt][3] + bv1[nt];
            if (HOUT) {
                __half* C = (__half*)Cv;
                *(__half2*)(C + o0) = __floats2half2_rn(v0, v1);
                *(__half2*)(C + o1) = __floats2half2_rn(v2, v3);
            } else {
                float* C = (float*)Cv;
                if (RES) {
                    v0 += res[o0]; v1 += res[o0 + 1];
                    v2 += res[o1]; v3 += res[o1 + 1];
                }
                *(float2*)(C + o0) = make_float2(v0, v1);
                *(float2*)(C + o1) = make_float2(v2, v3);
            }
        }
    }
}

// ---------------- attention: one warp per (b, h); 2-key softmax -----------
__global__ void attn_kernel(const __half* __restrict__ q,
                            const __half* __restrict__ kv2,
                            const __half* __restrict__ kv3,
                            __half* __restrict__ attn,
                            float* __restrict__ wout) {
    int gw   = (blockIdx.x * blockDim.x + threadIdx.x) >> 5;   // b*16 + h
    int lane = threadIdx.x & 31;
    int b = gw >> 4;
    int h = gw & 15;
    size_t qoff = (size_t)b*FEAT_     + h*HDIM + lane*4;
    size_t koff = (size_t)b*(2*FEAT_) + h*HDIM + lane*4;

    uint2 qr = *(const uint2*)(q   + qoff);
    uint2 k2r = *(const uint2*)(kv2 + koff);
    uint2 k3r = *(const uint2*)(kv3 + koff);
    uint2 v2r = *(const uint2*)(kv2 + koff + FEAT_);
    uint2 v3r = *(const uint2*)(kv3 + koff + FEAT_);

    float2 qa = __half22float2(*(__half2*)&qr.x);
    float2 qb = __half22float2(*(__half2*)&qr.y);
    float2 k2a = __half22float2(*(__half2*)&k2r.x);
    float2 k2b = __half22float2(*(__half2*)&k2r.y);
    float2 k3a = __half22float2(*(__half2*)&k3r.x);
    float2 k3b = __half22float2(*(__half2*)&k3r.y);
    float2 v2a = __half22float2(*(__half2*)&v2r.x);
    float2 v2b = __half22float2(*(__half2*)&v2r.y);
    float2 v3a = __half22float2(*(__half2*)&v3r.x);
    float2 v3b = __half22float2(*(__half2*)&v3r.y);

    float s2 = qa.x*k2a.x + qa.y*k2a.y + qb.x*k2b.x + qb.y*k2b.y;
    float s3 = qa.x*k3a.x + qa.y*k3a.y + qb.x*k3b.x + qb.y*k3b.y;
    #pragma unroll
    for (int o = 16; o; o >>= 1) {
        s2 += __shfl_xor_sync(0xffffffffu, s2, o);
        s3 += __shfl_xor_sync(0xffffffffu, s3, o);
    }
    const float scale = 0.08838834764831845f;   // 1/sqrt(128)
    s2 *= scale; s3 *= scale;
    float m  = fmaxf(s2, s3);
    float e2 = expf(s2 - m), e3 = expf(s3 - m);
    float inv = 1.f / (e2 + e3);
    float w2 = e2 * inv, w3 = e3 * inv;

    __half2 p0 = __floats2half2_rn(w2*v2a.x + w3*v3a.x, w2*v2a.y + w3*v3a.y);
    __half2 p1 = __floats2half2_rn(w2*v2b.x + w3*v3b.x, w2*v2b.y + w3*v3b.y);
    uint2 ov;
    ov.x = *(uint32_t*)&p0;
    ov.y = *(uint32_t*)&p1;
    *(uint2*)(attn + qoff) = ov;

    if (lane == 0) {
        wout[(size_t)gw*2]     = w2;
        wout[(size_t)gw*2 + 1] = w3;
    }
}

// ---------------- LayerNorm: one block per row ----------------------------
__global__ void ln_kernel(const float* __restrict__ y,
                          const float* __restrict__ lw,
                          const float* __restrict__ lb,
                          float* __restrict__ out) {
    __shared__ float shs[8], shq[8];
    int row = blockIdx.x, t = threadIdx.x;
    const float4* yr = (const float4*)(y + (size_t)row*CURD);
    float4 a = yr[t];
    float4 b = yr[256 + t];
    float s  = a.x+a.y+a.z+a.w + b.x+b.y+b.z+b.w;
    float qq = a.x*a.x+a.y*a.y+a.z*a.z+a.w*a.w
             + b.x*b.x+b.y*b.y+b.z*b.z+b.w*b.w;
    #pragma unroll
    for (int o = 16; o; o >>= 1) {
        s  += __shfl_xor_sync(0xffffffffu, s,  o);
        qq += __shfl_xor_sync(0xffffffffu, qq, o);
    }
    int warp = t >> 5;
    if ((t & 31) == 0) { shs[warp] = s; shq[warp] = qq; }
    __syncthreads();
    float S = 0.f, Q = 0.f;
    #pragma unroll
    for (int i = 0; i < 8; i++) { S += shs[i]; Q += shq[i]; }
    float mean = S * (1.f/2048.f);
    float inv  = rsqrtf(Q * (1.f/2048.f) - mean*mean + 1e-5f);

    const float4* lw4 = (const float4*)lw;
    const float4* lb4 = (const float4*)lb;
    float4* orow = (float4*)(out + (size_t)row*CURD);
    float4 w, z, o4;
    w = lw4[t];       z = lb4[t];
    o4.x = w.x*(a.x-mean)*inv + z.x;
    o4.y = w.y*(a.y-mean)*inv + z.y;
    o4.z = w.z*(a.z-mean)*inv + z.z;
    o4.w = w.w*(a.w-mean)*inv + z.w;
    orow[t] = o4;
    w = lw4[256+t];   z = lb4[256+t];
    o4.x = w.x*(b.x-mean)*inv + z.x;
    o4.y = w.y*(b.y-mean)*inv + z.y;
    o4.z = w.z*(b.z-mean)*inv + z.z;
    o4.w = w.w*(b.w-mean)*inv + z.w;
    orow[256+t] = o4;
}

// ---------------- launch ---------------------------------------------------
extern "C" void kernel_launch(void* const* d_in, const int* in_sizes, int n_in,
                              void* d_out, int out_size) {
    const float* x   = (const float*)d_in[0];
    const float* v2  = (const float*)d_in[1];
    const float* v3  = (const float*)d_in[2];
    const float* Wq  = (const float*)d_in[3];
    const float* bq  = (const float*)d_in[4];
    const float* Wk2 = (const float*)d_in[5];
    const float* bk2 = (const float*)d_in[6];
    const float* Wk3 = (const float*)d_in[7];
    const float* bk3 = (const float*)d_in[8];
    const float* Wv2 = (const float*)d_in[9];
    const float* bv2 = (const float*)d_in[10];
    const float* Wv3 = (const float*)d_in[11];
    const float* bv3 = (const float*)d_in[12];
    const float* Wo  = (const float*)d_in[13];
    const float* bo  = (const float*)d_in[14];
    const float* lw  = (const float*)d_in[15];
    const float* lb  = (const float*)d_in[16];
    float* out = (float*)d_out;

    __half *xh, *v2h, *v3h, *wqh, *wk2h, *wv2h, *wk3h, *wv3h, *woh;
    __half *qb, *kv2, *kv3, *attn;
    float *yb;
    cudaGetSymbolAddress((void**)&xh,   g_xh);
    cudaGetSymbolAddress((void**)&v2h,  g_v2h);
    cudaGetSymbolAddress((void**)&v3h,  g_v3h);
    cudaGetSymbolAddress((void**)&wqh,  g_wqh);
    cudaGetSymbolAddress((void**)&wk2h, g_wk2h);
    cudaGetSymbolAddress((void**)&wv2h, g_wv2h);
    cudaGetSymbolAddress((void**)&wk3h, g_wk3h);
    cudaGetSymbolAddress((void**)&wv3h, g_wv3h);
    cudaGetSymbolAddress((void**)&woh,  g_woh);
    cudaGetSymbolAddress((void**)&qb,   g_q);
    cudaGetSymbolAddress((void**)&kv2,  g_kv2);
    cudaGetSymbolAddress((void**)&kv3,  g_kv3);
    cudaGetSymbolAddress((void**)&attn, g_att);
    cudaGetSymbolAddress((void**)&yb,   g_y);

    cudaFuncSetAttribute((const void*)gemm_f16_kernel<false,true>,
                         cudaFuncAttributeMaxDynamicSharedMemorySize, SMEM_BYTES);
    cudaFuncSetAttribute((const void*)gemm_f16_kernel<true,false>,
                         cudaFuncAttributeMaxDynamicSharedMemorySize, SMEM_BYTES);

    const int RG = 2048, RT = 256;
    conv_h_kernel<<<RG, RT>>>(x,   xh,  (long long)B_*CURD/4);
    conv_h_kernel<<<RG, RT>>>(v2,  v2h, (long long)B_*FEAT_/4);
    conv_h_kernel<<<RG, RT>>>(v3,  v3h, (long long)B_*FEAT_/4);
    conv_h_kernel<<<RG, RT>>>(Wq,  wqh, (long long)FEAT_*CURD/4);
    conv_h_kernel<<<RG, RT>>>(Wk2, wk2h,(long long)FEAT_*FEAT_/4);
    conv_h_kernel<<<RG, RT>>>(Wv2, wv2h,(long long)FEAT_*FEAT_/4);
    conv_h_kernel<<<RG, RT>>>(Wk3, wk3h,(long long)FEAT_*FEAT_/4);
    conv_h_kernel<<<RG, RT>>>(Wv3, wv3h,(long long)FEAT_*FEAT_/4);
    conv_h_kernel<<<RG, RT>>>(Wo,  woh, (long long)CURD*FEAT_/4);

    dim3 blk(NTHREADS);
    // q = x @ Wq^T + bq          (fp16 out)
    gemm_f16_kernel<false,true><<<dim3(FEAT_/BN, B_/BM), blk, SMEM_BYTES>>>(
        xh, wqh, wqh, FEAT_, bq, bq, nullptr, qb, FEAT_, CURD);
    // [k2 | v2] = v2 @ [Wk2; Wv2]^T + [bk2; bv2]   (fp16 out)
    gemm_f16_kernel<false,true><<<dim3(2*FEAT_/BN, B_/BM), blk, SMEM_BYTES>>>(
        v2h, wk2h, wv2h, FEAT_, bk2, bv2, nullptr, kv2, 2*FEAT_, FEAT_);
    // [k3 | v3] = v3 @ [Wk3; Wv3]^T + [bk3; bv3]   (fp16 out)
    gemm_f16_kernel<false,true><<<dim3(2*FEAT_/BN, B_/BM), blk, SMEM_BYTES>>>(
        v3h, wk3h, wv3h, FEAT_, bk3, bv3, nullptr, kv3, 2*FEAT_, FEAT_);

    // attention + attn_weights (written to the tail of d_out)
    size_t woff = (size_t)out_size - (size_t)B_*HEADS_*2;
    attn_kernel<<<B_*HEADS_/8, 256>>>(qb, kv2, kv3, attn, out + woff);

    // y = x + attn @ Wo^T + bo   (residual fused, exact fp32 x; fp32 out)
    gemm_f16_kernel<true,false><<<dim3(CURD/BN, B_/BM), blk, SMEM_BYTES>>>(
        attn, woh, woh, CURD, bo, bo, x, yb, CURD, FEAT_);

    // LayerNorm -> d_out
    ln_kernel<<<B_, 256>>>(yb, lw, lb, out);
}

// round 12
// speedup vs baseline: 1.3364x; 1.0578x over previous
#include <cuda_runtime.h>
#include <cuda_fp16.h>
#include <cstdint>

#define B_    16384
#define CURD  2048
#define FEAT_ 2048
#define HEADS_ 16
#define HDIM  128

#define NTHREADS 256
#define BM 128
#define BN 128
#define BK 64
// per stage: A 128 rows x 128B = 16 KB, B 128 rows x 128B = 16 KB
#define A_STAGE   16384
#define STAGE_B   (2*A_STAGE)          // 32 KB
#define SMEM_BYTES (2*STAGE_B)         // 2 stages = 64 KB -> 2 CTAs/SM

// ---------------- scratch (device globals; no allocation allowed) ----------
__device__ __align__(16) __half g_xh [(size_t)B_*CURD];
__device__ __align__(16) __half g_v2h[(size_t)B_*FEAT_];
__device__ __align__(16) __half g_v3h[(size_t)B_*FEAT_];
__device__ __align__(16) __half g_wqh [(size_t)FEAT_*CURD];
__device__ __align__(16) __half g_wk2h[(size_t)FEAT_*FEAT_];
__device__ __align__(16) __half g_wv2h[(size_t)FEAT_*FEAT_];
__device__ __align__(16) __half g_wk3h[(size_t)FEAT_*FEAT_];
__device__ __align__(16) __half g_wv3h[(size_t)FEAT_*FEAT_];
__device__ __align__(16) __half g_woh [(size_t)CURD*FEAT_];
__device__ __align__(16) __half g_q  [(size_t)B_*FEAT_];
__device__ __align__(16) __half g_kv2[(size_t)B_*2*FEAT_];
__device__ __align__(16) __half g_kv3[(size_t)B_*2*FEAT_];
__device__ __align__(16) __half g_att[(size_t)B_*FEAT_];
__device__ __align__(16) float  g_y  [(size_t)B_*CURD];

// ---------------- helpers ----------------
__device__ __forceinline__ void cpa16(uint32_t s, const void* g) {
    asm volatile("cp.async.cg.shared.global [%0], [%1], 16;\n" :: "r"(s), "l"(g));
}

__device__ __forceinline__ void ldsm4(uint32_t* r, uint32_t addr) {
    asm volatile("ldmatrix.sync.aligned.m8n8.x4.shared.b16 {%0,%1,%2,%3}, [%4];"
        : "=r"(r[0]), "=r"(r[1]), "=r"(r[2]), "=r"(r[3]) : "r"(addr));
}

__device__ __forceinline__ void mma_f16(float* c, const uint32_t* a, const uint32_t* b) {
    asm volatile(
        "mma.sync.aligned.m16n8k16.row.col.f32.f16.f16.f32 "
        "{%0,%1,%2,%3}, {%4,%5,%6,%7}, {%8,%9}, {%0,%1,%2,%3};"
        : "+f"(c[0]), "+f"(c[1]), "+f"(c[2]), "+f"(c[3])
        : "r"(a[0]), "r"(a[1]), "r"(a[2]), "r"(a[3]),
          "r"(b[0]), "r"(b[1]));
}

// ---------------- fp32 -> fp16 conversions (merged launches) ----------------
// 3 activation buffers, equal size (B_*2048): z selects buffer
__global__ void convA_kernel(const float* __restrict__ i0, __half* o0,
                             const float* __restrict__ i1, __half* o1,
                             const float* __restrict__ i2, __half* o2) {
    const long long n4 = (long long)B_*2048/4;
    const float* in; __half* out;
    if      (blockIdx.z == 0) { in = i0; out = o0; }
    else if (blockIdx.z == 1) { in = i1; out = o1; }
    else                      { in = i2; out = o2; }
    long long i  = blockIdx.x * (long long)blockDim.x + threadIdx.x;
    long long st = (long long)gridDim.x * blockDim.x;
    const float4* in4 = (const float4*)in;
    __half2* oo = (__half2*)out;
    for (; i < n4; i += st) {
        float4 v = in4[i];
        oo[2*i]   = __floats2half2_rn(v.x, v.y);
        oo[2*i+1] = __floats2half2_rn(v.z, v.w);
    }
}

// 6 weight buffers, equal size (2048*2048): z selects buffer
__global__ void convW_kernel(const float* __restrict__ i0, __half* o0,
                             const float* __restrict__ i1, __half* o1,
                             const float* __restrict__ i2, __half* o2,
                             const float* __restrict__ i3, __half* o3,
                             const float* __restrict__ i4, __half* o4,
                             const float* __restrict__ i5, __half* o5) {
    const long long n4 = (long long)2048*2048/4;
    const float* in; __half* out;
    switch (blockIdx.z) {
        case 0: in = i0; out = o0; break;
        case 1: in = i1; out = o1; break;
        case 2: in = i2; out = o2; break;
        case 3: in = i3; out = o3; break;
        case 4: in = i4; out = o4; break;
        default: in = i5; out = o5; break;
    }
    long long i  = blockIdx.x * (long long)blockDim.x + threadIdx.x;
    long long st = (long long)gridDim.x * blockDim.x;
    const float4* in4 = (const float4*)in;
    __half2* oo = (__half2*)out;
    for (; i < n4; i += st) {
        float4 v = in4[i];
        oo[2*i]   = __floats2half2_rn(v.x, v.y);
        oo[2*i+1] = __floats2half2_rn(v.z, v.w);
    }
}

// ---------------- GEMM body (R8-validated core) -----------------------------
// C[M,N] = A[M,K] @ Wp[nloc0.., K]^T + biasP (+res), CTA tile 128x128,
// warp grid 2(M) x 4(N), warp tile 64x32, SW128 swizzle, ldmatrix,
// 2-stage cp.async double buffer. HOUT: fp16 C; else fp32 C (+res).
template<bool RES, bool HOUT>
__device__ __forceinline__ void gemm_body(
    const __half* A, const __half* Wp, const float* biasP, int nloc0,
    const float* res, void* Cv, int N, int K, int nb, int mb)
{
    extern __shared__ __align__(1024) char smem[];
    const uint32_t sbase = (uint32_t)__cvta_generic_to_shared(smem);

    const int tid  = threadIdx.x;
    const int warp = tid >> 5, lane = tid & 31;
    const int wm = warp & 1;
    const int wn = warp >> 1;
    const int qr = lane >> 2, qc = lane & 3;

    // staging: per thread one half-row (64B = 4x16B)
    const int srow = tid >> 1;
    const int scol = (tid & 1) * 64;
    const uint32_t sxor = (uint32_t)((srow & 7) << 4);
    const __half* Ag = A  + (size_t)(mb*BM + srow)*K + scol/2;
    const __half* Bg = Wp + (size_t)(nloc0 + srow)*K + scol/2;

    // ldmatrix addressing
    const int j  = lane >> 3;
    const int rr = lane & 7;
    const uint32_t fxor = (uint32_t)(rr << 4);
    const uint32_t aRow  = (uint32_t)(wm*64 + (j&1)*8 + rr);
    const uint32_t aKoff = (uint32_t)((j>>1)*16);
    const uint32_t bRow  = (uint32_t)(wn*32 + (j>>1)*8 + rr);
    const uint32_t bKoff = (uint32_t)((j&1)*16);

    float acc[4][4][4];
    #pragma unroll
    for (int i = 0; i < 4; i++)
        #pragma unroll
        for (int jn = 0; jn < 4; jn++)
            #pragma unroll
            for (int l = 0; l < 4; l++) acc[i][jn][l] = 0.f;

    const int KT = K / BK;

    // prologue: stage 0
    {
        const uint32_t sA = sbase, sB = sbase + A_STAGE;
        #pragma unroll
        for (int i = 0; i < 4; i++) {
            uint32_t c = ((uint32_t)(scol + i*16)) ^ sxor;
            cpa16(sA + srow*128 + c, Ag + i*8);
            cpa16(sB + srow*128 + c, Bg + i*8);
        }
        asm volatile("cp.async.commit_group;\n" ::);
        asm volatile("cp.async.wait_group 0;\n" ::);
        __syncthreads();
    }

    int buf = 0;
    for (int kt = 0; kt < KT; kt++) {
        if (kt + 1 < KT) {
            const int nbuf = buf ^ 1;
            const uint32_t sA = sbase + nbuf*STAGE_B, sB = sA + A_STAGE;
            const __half* Agk = Ag + (kt+1)*BK;
            const __half* Bgk = Bg + (kt+1)*BK;
            #pragma unroll
            for (int i = 0; i < 4; i++) {
                uint32_t c = ((uint32_t)(scol + i*16)) ^ sxor;
                cpa16(sA + srow*128 + c, Agk + i*8);
                cpa16(sB + srow*128 + c, Bgk + i*8);
            }
            asm volatile("cp.async.commit_group;\n" ::);
        }

        const uint32_t aBase = sbase + buf*STAGE_B + aRow*128;
        const uint32_t bBase = sbase + buf*STAGE_B + A_STAGE + bRow*128;
        #pragma unroll
        for (int ks = 0; ks < BK/16; ks++) {
            uint32_t afr[4][4];
            const uint32_t ac = ((uint32_t)(ks*32) + aKoff) ^ fxor;
            #pragma unroll
            for (int mt = 0; mt < 4; mt++)
                ldsm4(afr[mt], aBase + mt*16*128 + ac);
            uint32_t bfr[8];
            const uint32_t bc = ((uint32_t)(ks*32) + bKoff) ^ fxor;
            ldsm4(bfr,     bBase + bc);
            ldsm4(bfr + 4, bBase + 16*128 + bc);
            #pragma unroll
            for (int mt = 0; mt < 4; mt++)
                #pragma unroll
                for (int nt = 0; nt < 4; nt++)
                    mma_f16(acc[mt][nt], afr[mt], bfr + nt*2);
        }

        asm volatile("cp.async.wait_group 0;\n" ::);
        __syncthreads();
        buf ^= 1;
    }

    // epilogue
    float bv0[4], bv1[4];
    #pragma unroll
    for (int nt = 0; nt < 4; nt++) {
        int cl = nloc0 + wn*32 + nt*8 + qc*2;
        bv0[nt] = biasP[cl];
        bv1[nt] = biasP[cl + 1];
    }
    #pragma unroll
    for (int mt = 0; mt < 4; mt++) {
        int r0 = mb*BM + wm*64 + mt*16 + qr;
        #pragma unroll
        for (int nt = 0; nt < 4; nt++) {
            int c0 = nb*BN + wn*32 + nt*8 + qc*2;
            size_t o0 = (size_t)r0*N + c0;
            size_t o1 = o0 + (size_t)8*N;
            float v0 = acc[mt][nt][0] + bv0[nt];
            float v1 = acc[mt][nt][1] + bv1[nt];
            float v2 = acc[mt][nt][2] + bv0[nt];
            float v3 = acc[mt][nt][3] + bv1[nt];
            if (HOUT) {
                __half* C = (__half*)Cv;
                *(__half2*)(C + o0) = __floats2half2_rn(v0, v1);
                *(__half2*)(C + o1) = __floats2half2_rn(v2, v3);
            } else {
                float* C = (float*)Cv;
                if (RES) {
                    v0 += res[o0]; v1 += res[o0 + 1];
                    v2 += res[o1]; v3 += res[o1 + 1];
                }
                *(float2*)(C + o0) = make_float2(v0, v1);
                *(float2*)(C + o1) = make_float2(v2, v3);
            }
        }
    }
}

// ---------------- fused projection GEMM: q + [k2|v2] + [k3|v3] in ONE launch
// 1-D grid of 2048 + 4096 + 4096 = 10240 CTAs; nb-fastest within segment.
__global__ __launch_bounds__(NTHREADS, 2)
void gemm_proj3_kernel(const __half* __restrict__ xh,
                       const __half* __restrict__ v2h,
                       const __half* __restrict__ v3h,
                       const __half* __restrict__ wq,
                       const __half* __restrict__ wk2, const __half* __restrict__ wv2,
                       const __half* __restrict__ wk3, const __half* __restrict__ wv3,
                       const float* __restrict__ bq,
                       const float* __restrict__ bk2, const float* __restrict__ bv2,
                       const float* __restrict__ bk3, const float* __restrict__ bv3,
                       __half* __restrict__ qb, __half* __restrict__ kv2,
                       __half* __restrict__ kv3) {
    const int bx = blockIdx.x;
    const __half* A; const __half* W0; const __half* W1;
    const float* b0; const float* b1; __half* C;
    int idx, NB, N;
    if (bx < 2048)      { idx = bx;        NB = 16; N = 2048;
                          A = xh;  W0 = wq;  W1 = wq;  b0 = bq;  b1 = bq;  C = qb;  }
    else if (bx < 6144) { idx = bx - 2048; NB = 32; N = 4096;
                          A = v2h; W0 = wk2; W1 = wv2; b0 = bk2; b1 = bv2; C = kv2; }
    else                { idx = bx - 6144; NB = 32; N = 4096;
                          A = v3h; W0 = wk3; W1 = wv3; b0 = bk3; b1 = bv3; C = kv3; }
    const int nb = idx % NB;
    const int mb = idx / NB;

    const __half* Wp; const float* biasP; int nloc0;
    if (nb*BN < 2048) { Wp = W0; biasP = b0; nloc0 = nb*BN; }
    else              { Wp = W1; biasP = b1; nloc0 = nb*BN - 2048; }

    gemm_body<false, true>(A, Wp, biasP, nloc0, nullptr, C, N, CURD, nb, mb);
}

// ---------------- Wo GEMM: y = x + attn @ Wo^T + bo (fp32 out) -------------
__global__ __launch_bounds__(NTHREADS, 2)
void gemm_wo_kernel(const __half* __restrict__ attn,
                    const __half* __restrict__ wo,
                    const float* __restrict__ bo,
                    const float* __restrict__ res,
                    float* __restrict__ y) {
    const int nb = blockIdx.x, mb = blockIdx.y;
    gemm_body<true, false>(attn, wo, bo, nb*BN, res, y, CURD, FEAT_, nb, mb);
}

// ---------------- attention: one warp per (b, h); 2-key softmax -----------
__global__ void attn_kernel(const __half* __restrict__ q,
                            const __half* __restrict__ kv2,
                            const __half* __restrict__ kv3,
                            __half* __restrict__ attn,
                            float* __restrict__ wout) {
    int gw   = (blockIdx.x * blockDim.x + threadIdx.x) >> 5;   // b*16 + h
    int lane = threadIdx.x & 31;
    int b = gw >> 4;
    int h = gw & 15;
    size_t qoff = (size_t)b*FEAT_     + h*HDIM + lane*4;
    size_t koff = (size_t)b*(2*FEAT_) + h*HDIM + lane*4;

    uint2 qr = *(const uint2*)(q   + qoff);
    uint2 k2r = *(const uint2*)(kv2 + koff);
    uint2 k3r = *(const uint2*)(kv3 + koff);
    uint2 v2r = *(const uint2*)(kv2 + koff + FEAT_);
    uint2 v3r = *(const uint2*)(kv3 + koff + FEAT_);

    float2 qa = __half22float2(*(__half2*)&qr.x);
    float2 qb = __half22float2(*(__half2*)&qr.y);
    float2 k2a = __half22float2(*(__half2*)&k2r.x);
    float2 k2b = __half22float2(*(__half2*)&k2r.y);
    float2 k3a = __half22float2(*(__half2*)&k3r.x);
    float2 k3b = __half22float2(*(__half2*)&k3r.y);
    float2 v2a = __half22float2(*(__half2*)&v2r.x);
    float2 v2b = __half22float2(*(__half2*)&v2r.y);
    float2 v3a = __half22float2(*(__half2*)&v3r.x);
    float2 v3b = __half22float2(*(__half2*)&v3r.y);

    float s2 = qa.x*k2a.x + qa.y*k2a.y + qb.x*k2b.x + qb.y*k2b.y;
    float s3 = qa.x*k3a.x + qa.y*k3a.y + qb.x*k3b.x + qb.y*k3b.y;
    #pragma unroll
    for (int o = 16; o; o >>= 1) {
        s2 += __shfl_xor_sync(0xffffffffu, s2, o);
        s3 += __shfl_xor_sync(0xffffffffu, s3, o);
    }
    const float scale = 0.08838834764831845f;   // 1/sqrt(128)
    s2 *= scale; s3 *= scale;
    float m  = fmaxf(s2, s3);
    float e2 = expf(s2 - m), e3 = expf(s3 - m);
    float inv = 1.f / (e2 + e3);
    float w2 = e2 * inv, w3 = e3 * inv;

    __half2 p0 = __floats2half2_rn(w2*v2a.x + w3*v3a.x, w2*v2a.y + w3*v3a.y);
    __half2 p1 = __floats2half2_rn(w2*v2b.x + w3*v3b.x, w2*v2b.y + w3*v3b.y);
    uint2 ov;
    ov.x = *(uint32_t*)&p0;
    ov.y = *(uint32_t*)&p1;
    *(uint2*)(attn + qoff) = ov;

    if (lane == 0) {
        wout[(size_t)gw*2]     = w2;
        wout[(size_t)gw*2 + 1] = w3;
    }
}

// ---------------- LayerNorm: one block per row ----------------------------
__global__ void ln_kernel(const float* __restrict__ y,
                          const float* __restrict__ lw,
                          const float* __restrict__ lb,
                          float* __restrict__ out) {
    __shared__ float shs[8], shq[8];
    int row = blockIdx.x, t = threadIdx.x;
    const float4* yr = (const float4*)(y + (size_t)row*CURD);
    float4 a = yr[t];
    float4 b = yr[256 + t];
    float s  = a.x+a.y+a.z+a.w + b.x+b.y+b.z+b.w;
    float qq = a.x*a.x+a.y*a.y+a.z*a.z+a.w*a.w
             + b.x*b.x+b.y*b.y+b.z*b.z+b.w*b.w;
    #pragma unroll
    for (int o = 16; o; o >>= 1) {
        s  += __shfl_xor_sync(0xffffffffu, s,  o);
        qq += __shfl_xor_sync(0xffffffffu, qq, o);
    }
    int warp = t >> 5;
    if ((t & 31) == 0) { shs[warp] = s; shq[warp] = qq; }
    __syncthreads();
    float S = 0.f, Q = 0.f;
    #pragma unroll
    for (int i = 0; i < 8; i++) { S += shs[i]; Q += shq[i]; }
    float mean = S * (1.f/2048.f);
    float inv  = rsqrtf(Q * (1.f/2048.f) - mean*mean + 1e-5f);

    const float4* lw4 = (const float4*)lw;
    const float4* lb4 = (const float4*)lb;
    float4* orow = (float4*)(out + (size_t)row*CURD);
    float4 w, z, o4;
    w = lw4[t];       z = lb4[t];
    o4.x = w.x*(a.x-mean)*inv + z.x;
    o4.y = w.y*(a.y-mean)*inv + z.y;
    o4.z = w.z*(a.z-mean)*inv + z.z;
    o4.w = w.w*(a.w-mean)*inv + z.w;
    orow[t] = o4;
    w = lw4[256+t];   z = lb4[256+t];
    o4.x = w.x*(b.x-mean)*inv + z.x;
    o4.y = w.y*(b.y-mean)*inv + z.y;
    o4.z = w.z*(b.z-mean)*inv + z.z;
    o4.w = w.w*(b.w-mean)*inv + z.w;
    orow[256+t] = o4;
}

// ---------------- launch ---------------------------------------------------
extern "C" void kernel_launch(void* const* d_in, const int* in_sizes, int n_in,
                              void* d_out, int out_size) {
    const float* x   = (const float*)d_in[0];
    const float* v2  = (const float*)d_in[1];
    const float* v3  = (const float*)d_in[2];
    const float* Wq  = (const float*)d_in[3];
    const float* bq  = (const float*)d_in[4];
    const float* Wk2 = (const float*)d_in[5];
    const float* bk2 = (const float*)d_in[6];
    const float* Wk3 = (const float*)d_in[7];
    const float* bk3 = (const float*)d_in[8];
    const float* Wv2 = (const float*)d_in[9];
    const float* bv2 = (const float*)d_in[10];
    const float* Wv3 = (const float*)d_in[11];
    const float* bv3 = (const float*)d_in[12];
    const float* Wo  = (const float*)d_in[13];
    const float* bo  = (const float*)d_in[14];
    const float* lw  = (const float*)d_in[15];
    const float* lb  = (const float*)d_in[16];
    float* out = (float*)d_out;

    __half *xh, *v2h, *v3h, *wqh, *wk2h, *wv2h, *wk3h, *wv3h, *woh;
    __half *qb, *kv2, *kv3, *attn;
    float *yb;
    cudaGetSymbolAddress((void**)&xh,   g_xh);
    cudaGetSymbolAddress((void**)&v2h,  g_v2h);
    cudaGetSymbolAddress((void**)&v3h,  g_v3h);
    cudaGetSymbolAddress((void**)&wqh,  g_wqh);
    cudaGetSymbolAddress((void**)&wk2h, g_wk2h);
    cudaGetSymbolAddress((void**)&wv2h, g_wv2h);
    cudaGetSymbolAddress((void**)&wk3h, g_wk3h);
    cudaGetSymbolAddress((void**)&wv3h, g_wv3h);
    cudaGetSymbolAddress((void**)&woh,  g_woh);
    cudaGetSymbolAddress((void**)&qb,   g_q);
    cudaGetSymbolAddress((void**)&kv2,  g_kv2);
    cudaGetSymbolAddress((void**)&kv3,  g_kv3);
    cudaGetSymbolAddress((void**)&attn, g_att);
    cudaGetSymbolAddress((void**)&yb,   g_y);

    cudaFuncSetAttribute((const void*)gemm_proj3_kernel,
                         cudaFuncAttributeMaxDynamicSharedMemorySize, SMEM_BYTES);
    cudaFuncSetAttribute((const void*)gemm_wo_kernel,
                         cudaFuncAttributeMaxDynamicSharedMemorySize, SMEM_BYTES);

    // conversions: 2 merged launches
    convA_kernel<<<dim3(2048, 1, 3), 256>>>(x, xh, v2, v2h, v3, v3h);
    convW_kernel<<<dim3(1024, 1, 6), 256>>>(Wq, wqh, Wk2, wk2h, Wv2, wv2h,
                                            Wk3, wk3h, Wv3, wv3h, Wo, woh);

    // fused projections: q + [k2|v2] + [k3|v3]
    gemm_proj3_kernel<<<10240, NTHREADS, SMEM_BYTES>>>(
        xh, v2h, v3h, wqh, wk2h, wv2h, wk3h, wv3h,
        bq, bk2, bv2, bk3, bv3, qb, kv2, kv3);

    // attention + attn_weights (written to the tail of d_out)
    size_t woff = (size_t)out_size - (size_t)B_*HEADS_*2;
    attn_kernel<<<B_*HEADS_/8, 256>>>(qb, kv2, kv3, attn, out + woff);

    // y = x + attn @ Wo^T + bo
    gemm_wo_kernel<<<dim3(CURD/BN, B_/BM), NTHREADS, SMEM_BYTES>>>(
        attn, woh, bo, x, yb);

    // LayerNorm -> d_out
    ln_kernel<<<B_, 256>>>(yb, lw, lb, out);
}